// round 3
// baseline (speedup 1.0000x reference)
#include <cuda_runtime.h>
#include <cstdint>

typedef unsigned long long u64;

// ---------------------------------------------------------------------------
// Parameter block. Layer-1 weights per hidden unit h: 16 duplicated float2
// pairs, ordered for ulonglong2 (LDS.128) loads:
//   [bias, w_k0][w_k4, w_k6][s0,s1][s2,s3][s4,s5][f0,f1][f2,f3][f4,f5]
// where s* = straight weights for k={1,2,3,5,7,8}, f* = FLIP'd weights for
// the same k order. FLIP fixes {0,4,6}; those products + bias are shared.
// Minv needed only for columns 3..8 (dm rows 0..2 are zero).
// w2 duplicated as pairs for packed layer-2 accumulation.
// ---------------------------------------------------------------------------
struct __align__(16) Params {
    float2 Wj[24][16];
    float2 Wn[24][16];
    float2 Mi6[9][6];
    float2 w2j[24];
    float2 w2n[24];
    float  jb2, nb2x2;
    float  pad[2];
};
__device__ Params g_p;

__global__ void prep_kernel(const float* __restrict__ jw1, const float* __restrict__ jb1,
                            const float* __restrict__ jw2, const float* __restrict__ jb2,
                            const float* __restrict__ nw1, const float* __restrict__ nb1,
                            const float* __restrict__ nw2, const float* __restrict__ nb2,
                            const float* __restrict__ M,   const float* __restrict__ Mi)
{
    (void)M;
    const int S[6] = {1, 2, 3, 5, 7, 8};  // straight moment index
    const int F[6] = {2, 1, 5, 3, 8, 7};  // FLIP of S (weight index for flipped input)
    int t = threadIdx.x;
    if (t < 24) {
        int h = t;
        float a;
        g_p.Wj[h][0] = make_float2(jb1[h], jb1[h]);
        g_p.Wn[h][0] = make_float2(nb1[h], nb1[h]);
        a = jw1[h*9+0]; g_p.Wj[h][1] = make_float2(a, a);
        a = jw1[h*9+4]; g_p.Wj[h][2] = make_float2(a, a);
        a = jw1[h*9+6]; g_p.Wj[h][3] = make_float2(a, a);
        a = nw1[h*9+0]; g_p.Wn[h][1] = make_float2(a, a);
        a = nw1[h*9+4]; g_p.Wn[h][2] = make_float2(a, a);
        a = nw1[h*9+6]; g_p.Wn[h][3] = make_float2(a, a);
        for (int j = 0; j < 6; ++j) {
            a = jw1[h*9+S[j]]; g_p.Wj[h][4+j]  = make_float2(a, a);
            a = jw1[h*9+F[j]]; g_p.Wj[h][10+j] = make_float2(a, a);
            a = nw1[h*9+S[j]]; g_p.Wn[h][4+j]  = make_float2(a, a);
            a = nw1[h*9+F[j]]; g_p.Wn[h][10+j] = make_float2(a, a);
        }
        g_p.w2j[h] = make_float2(jw2[h], jw2[h]);
        g_p.w2n[h] = make_float2(nw2[h], nw2[h]);
    }
    if (t < 9)
        for (int c = 0; c < 6; ++c) {
            float v = Mi[t * 9 + 3 + c];
            g_p.Mi6[t][c] = make_float2(v, v);
        }
    if (t == 0) { g_p.jb2 = jb2[0]; g_p.nb2x2 = 2.0f * nb2[0]; }
}

// ---------------------------------------------------------------------------
// f32x2 packed helpers
// ---------------------------------------------------------------------------
__device__ __forceinline__ u64 pk2(float lo, float hi) {
    u64 r; asm("mov.b64 %0, {%1, %2};" : "=l"(r) : "f"(lo), "f"(hi)); return r;
}
__device__ __forceinline__ void upk2(u64 v, float& lo, float& hi) {
    asm("mov.b64 {%0, %1}, %2;" : "=f"(lo), "=f"(hi) : "l"(v));
}
__device__ __forceinline__ u64 ffma2(u64 a, u64 b, u64 c) {
    u64 d; asm("fma.rn.f32x2 %0, %1, %2, %3;" : "=l"(d) : "l"(a), "l"(b), "l"(c)); return d;
}
__device__ __forceinline__ u64 fmul2(u64 a, u64 b) {
    u64 d; asm("mul.rn.f32x2 %0, %1, %2;" : "=l"(d) : "l"(a), "l"(b)); return d;
}
__device__ __forceinline__ u64 fadd2(u64 a, u64 b) {
    u64 d; asm("add.rn.f32x2 %0, %1, %2;" : "=l"(d) : "l"(a), "l"(b)); return d;
}
__device__ __forceinline__ float rcpa(float x) {
    float r; asm("rcp.approx.f32 %0, %1;" : "=f"(r) : "f"(x)); return r;
}
// relu on both packed halves; FMNMX issues on the alu pipe (fma pipe untouched)
__device__ __forceinline__ u64 relu2(u64 x) {
    float a, b; upk2(x, a, b);
    return pk2(fmaxf(a, 0.0f), fmaxf(b, 0.0f));
}

#define NEGM 0x8000000080000000ULL

// ---------------------------------------------------------------------------
// Layer-1 + packed layer-2 over 24 hidden units.
// SUM_MODE=false: straight -> oS*, flipped -> oF* (j-network).
// SUM_MODE=true : relus summed, single packed w2 fma (n-network).
// Accumulator lanes = cells, so no horizontal reduction is ever needed.
// ---------------------------------------------------------------------------
template <bool SUM_MODE>
__device__ __forceinline__ void mlp24(const ulonglong2* __restrict__ Wv,
                                      const u64* __restrict__ w2pk,
                                      const u64 (&mA)[9], const u64 (&mB)[9],
                                      u64& oSA, u64& oSB, u64& oFA, u64& oFB)
{
    #pragma unroll 4
    for (int h = 0; h < 24; ++h) {
        const ulonglong2* w = Wv + h * 8;
        ulonglong2 L0 = w[0], L1 = w[1];
        u64 pA = ffma2(L0.y, mA[0], L0.x);
        u64 pB = ffma2(L0.y, mB[0], L0.x);
        pA = ffma2(L1.x, mA[4], pA);
        pB = ffma2(L1.x, mB[4], pB);
        pA = ffma2(L1.y, mA[6], pA);
        pB = ffma2(L1.y, mB[6], pB);
        ulonglong2 L2 = w[2], L3 = w[3], L4 = w[4];
        ulonglong2 L5 = w[5], L6 = w[6], L7 = w[7];
        u64 sA = pA, sB = pB, fA = pA, fB = pB;
        sA = ffma2(L2.x, mA[1], sA);  sB = ffma2(L2.x, mB[1], sB);
        fA = ffma2(L5.x, mA[1], fA);  fB = ffma2(L5.x, mB[1], fB);
        sA = ffma2(L2.y, mA[2], sA);  sB = ffma2(L2.y, mB[2], sB);
        fA = ffma2(L5.y, mA[2], fA);  fB = ffma2(L5.y, mB[2], fB);
        sA = ffma2(L3.x, mA[3], sA);  sB = ffma2(L3.x, mB[3], sB);
        fA = ffma2(L6.x, mA[3], fA);  fB = ffma2(L6.x, mB[3], fB);
        sA = ffma2(L3.y, mA[5], sA);  sB = ffma2(L3.y, mB[5], sB);
        fA = ffma2(L6.y, mA[5], fA);  fB = ffma2(L6.y, mB[5], fB);
        sA = ffma2(L4.x, mA[7], sA);  sB = ffma2(L4.x, mB[7], sB);
        fA = ffma2(L7.x, mA[7], fA);  fB = ffma2(L7.x, mB[7], fB);
        sA = ffma2(L4.y, mA[8], sA);  sB = ffma2(L4.y, mB[8], sB);
        fA = ffma2(L7.y, mA[8], fA);  fB = ffma2(L7.y, mB[8], fB);

        u64 w2 = w2pk[h];
        u64 rsA = relu2(sA), rsB = relu2(sB);
        u64 rfA = relu2(fA), rfB = relu2(fB);
        if (SUM_MODE) {
            oSA = ffma2(w2, fadd2(rsA, rfA), oSA);
            oSB = ffma2(w2, fadd2(rsB, rfB), oSB);
        } else {
            oSA = ffma2(w2, rsA, oSA);
            oSB = ffma2(w2, rsB, oSB);
            oFA = ffma2(w2, rfA, oFA);
            oFB = ffma2(w2, rfB, oFB);
        }
    }
}

// Sparse hardcoded moment transform (M stencil is 0/±1/±2/4, -1/3 folded).
__device__ __forceinline__ void moments(const u64 (&f)[9], u64 (&m)[9],
                                        u64 c_m2, u64 c_4, u64 c_m13)
{
    u64 nf3 = f[3] ^ NEGM, nf4 = f[4] ^ NEGM, nf7 = f[7] ^ NEGM, nf8 = f[8] ^ NEGM;
    u64 s58 = fadd2(f[5], f[8]);
    u64 s67 = fadd2(f[6], f[7]);
    u64 d58 = fadd2(f[5], nf8);
    u64 d67 = fadd2(f[6], nf7);
    u64 t13 = fadd2(f[1], nf3);
    u64 t24 = fadd2(f[2], nf4);
    u64 s13 = fadd2(f[1], f[3]);
    u64 s24 = fadd2(f[2], f[4]);
    u64 u = fadd2(s58, s67 ^ NEGM);        // f5-f6-f7+f8
    u64 v = fadd2(d58, d67);               // f5+f6-f7-f8
    u64 Q = fadd2(s58, s67);
    u64 P = fadd2(s13, s24);
    m[0] = fadd2(f[0], fadd2(P, Q));
    m[1] = fadd2(t13, u);
    m[2] = fadd2(t24, v);
    m[4] = fadd2(d58, d67 ^ NEGM);         // f5-f6+f7-f8
    m[6] = ffma2(P, c_m2, ffma2(Q, c_4, f[0]));
    m[7] = ffma2(t13, c_m2, fmul2(u, c_4));
    m[8] = ffma2(t24, c_m2, fmul2(v, c_4));
    m[3] = ffma2(m[0], c_m13, fadd2(s13, Q));
    m[5] = ffma2(m[0], c_m13, fadd2(s24, Q));
}

__global__ __launch_bounds__(256, 2) void lbm_kernel(const float* __restrict__ f,
                                                     float* __restrict__ out, int N)
{
    __shared__ Params sp;
    {
        const uint4* src = reinterpret_cast<const uint4*>(&g_p);
        uint4* dst = reinterpret_cast<uint4*>(&sp);
        const int n16 = (int)(sizeof(Params) / 16);
        for (int i = threadIdx.x; i < n16; i += blockDim.x) dst[i] = src[i];
    }
    __syncthreads();

    long long idx = (long long)(blockIdx.x * blockDim.x + threadIdx.x) * 4;
    if (idx >= N) return;

    const u64 c_m2  = pk2(-2.0f, -2.0f);
    const u64 c_4   = pk2(4.0f, 4.0f);
    const u64 c_m13 = pk2(-1.0f / 3.0f, -1.0f / 3.0f);

    // ---- load f, compute moments; f registers die here (reloaded at output)
    u64 mA[9], mB[9];
    {
        u64 fA[9], fB[9];
        #pragma unroll
        for (int i = 0; i < 9; ++i) {
            float4 v = *reinterpret_cast<const float4*>(f + (size_t)i * N + idx);
            fA[i] = pk2(v.x, v.y);
            fB[i] = pk2(v.z, v.w);
        }
        moments(fA, mA, c_m2, c_4, c_m13);
        moments(fB, mB, c_m2, c_4, c_m13);
    }

    // ---- MLPs (packed layer-2; lanes = cells)
    const ulonglong2* Wj = reinterpret_cast<const ulonglong2*>(sp.Wj);
    const ulonglong2* Wn = reinterpret_cast<const ulonglong2*>(sp.Wn);
    const u64* w2j = reinterpret_cast<const u64*>(sp.w2j);
    const u64* w2n = reinterpret_cast<const u64*>(sp.w2n);

    u64 jxA = pk2(sp.jb2, sp.jb2),     jxB = jxA;   // straight -> tau_jx
    u64 jyA = jxA,                      jyB = jxA;  // flipped  -> tau_jy
    u64 nnA = pk2(sp.nb2x2, sp.nb2x2), nnB = nnA;   // summed   -> tau_n
    u64 dumA = 0, dumB = 0;

    mlp24<false>(Wj, w2j, mA, mB, jxA, jxB, jyA, jyB);
    mlp24<true >(Wn, w2n, mA, mB, nnA, nnB, dumA, dumB);

    float jx0, jx1, jx2, jx3, jy0, jy1, jy2, jy3, nn0, nn1, nn2, nn3;
    upk2(jxA, jx0, jx1); upk2(jxB, jx2, jx3);
    upk2(jyA, jy0, jy1); upk2(jyB, jy2, jy3);
    upk2(nnA, nn0, nn1); upk2(nnB, nn2, nn3);

    // -1/tau = rcp(-(0.5+exp(a)))  (exact sign flip through rcp)
    u64 ntnA = pk2(rcpa(-0.5f - __expf(nn0)), rcpa(-0.5f - __expf(nn1)));
    u64 ntnB = pk2(rcpa(-0.5f - __expf(nn2)), rcpa(-0.5f - __expf(nn3)));
    u64 ntxA = pk2(rcpa(-0.5f - __expf(jx0)), rcpa(-0.5f - __expf(jx1)));
    u64 ntxB = pk2(rcpa(-0.5f - __expf(jx2)), rcpa(-0.5f - __expf(jx3)));
    u64 ntyA = pk2(rcpa(-0.5f - __expf(jy0)), rcpa(-0.5f - __expf(jy1)));
    u64 ntyB = pk2(rcpa(-0.5f - __expf(jy2)), rcpa(-0.5f - __expf(jy3)));

    // ---- ndm = (meq - m)/tau for rows 3..8 (rows 0..2 are zero)
    float r0, r1, r2, r3;
    upk2(mA[0], r0, r1);
    upk2(mB[0], r2, r3);
    u64 rAn = pk2(rcpa(-r0), rcpa(-r1));   // -1/rho
    u64 rBn = pk2(rcpa(-r2), rcpa(-r3));
    u64 jxrA = fmul2(mA[1], rAn), jxrB = fmul2(mB[1], rBn);  // -jx/rho
    u64 jyrA = fmul2(mA[2], rAn), jyrB = fmul2(mB[2], rBn);
    u64 q3A = fmul2(mA[1], jxrA), q3B = fmul2(mB[1], jxrB);  // -jx^2/rho
    u64 q4A = fmul2(mA[2], jxrA), q4B = fmul2(mB[2], jxrB);
    u64 q5A = fmul2(mA[2], jyrA), q5B = fmul2(mB[2], jyrB);

    const u64 c_ninv = pk2(-1.0f / 0.7f, -1.0f / 0.7f);
    u64 dmA[6], dmB[6];
    dmA[0] = fmul2(fadd2(mA[3], q3A), c_ninv);
    dmB[0] = fmul2(fadd2(mB[3], q3B), c_ninv);
    dmA[1] = fmul2(fadd2(mA[4], q4A), c_ninv);
    dmB[1] = fmul2(fadd2(mB[4], q4B), c_ninv);
    dmA[2] = fmul2(fadd2(mA[5], q5A), c_ninv);
    dmB[2] = fmul2(fadd2(mB[5], q5B), c_ninv);
    dmA[3] = fmul2(mA[6], ntnA);
    dmB[3] = fmul2(mB[6], ntnB);
    dmA[4] = fmul2(mA[7], ntxA);
    dmB[4] = fmul2(mB[7], ntxB);
    dmA[5] = fmul2(mA[8], ntyA);
    dmB[5] = fmul2(mB[8], ntyB);

    // ---- out_i = f_i + sum_c Minv[i][3+c] * ndm[c]   (f reloaded, L2-hot)
    const ulonglong2* Mi6 = reinterpret_cast<const ulonglong2*>(sp.Mi6);
    #pragma unroll
    for (int i = 0; i < 9; ++i) {
        float4 v = __ldg(reinterpret_cast<const float4*>(f + (size_t)i * N + idx));
        u64 a = pk2(v.x, v.y);
        u64 b = pk2(v.z, v.w);
        ulonglong2 W0 = Mi6[i * 3 + 0];
        ulonglong2 W1 = Mi6[i * 3 + 1];
        ulonglong2 W2 = Mi6[i * 3 + 2];
        a = ffma2(W0.x, dmA[0], a);  b = ffma2(W0.x, dmB[0], b);
        a = ffma2(W0.y, dmA[1], a);  b = ffma2(W0.y, dmB[1], b);
        a = ffma2(W1.x, dmA[2], a);  b = ffma2(W1.x, dmB[2], b);
        a = ffma2(W1.y, dmA[3], a);  b = ffma2(W1.y, dmB[3], b);
        a = ffma2(W2.x, dmA[4], a);  b = ffma2(W2.x, dmB[4], b);
        a = ffma2(W2.y, dmA[5], a);  b = ffma2(W2.y, dmB[5], b);
        float o0, o1, o2, o3;
        upk2(a, o0, o1);
        upk2(b, o2, o3);
        *reinterpret_cast<float4*>(out + (size_t)i * N + idx) = make_float4(o0, o1, o2, o3);
    }
}

extern "C" void kernel_launch(void* const* d_in, const int* in_sizes, int n_in,
                              void* d_out, int out_size)
{
    // input order: f, j_w1, j_b1, j_w2, j_b2, n_w1, n_b1, n_w2, n_b2, M, Minv
    const float* f = (const float*)d_in[0];
    prep_kernel<<<1, 96>>>((const float*)d_in[1], (const float*)d_in[2],
                           (const float*)d_in[3], (const float*)d_in[4],
                           (const float*)d_in[5], (const float*)d_in[6],
                           (const float*)d_in[7], (const float*)d_in[8],
                           (const float*)d_in[9], (const float*)d_in[10]);

    int N = in_sizes[0] / 9;                 // 2048*2048 cells
    int threads = (N + 3) / 4;               // 4 cells per thread
    int block = 256;
    int grid = (threads + block - 1) / block;
    lbm_kernel<<<grid, block>>>(f, (float*)d_out, N);
}

// round 4
// speedup vs baseline: 1.2601x; 1.2601x over previous
#include <cuda_runtime.h>
#include <cstdint>

typedef unsigned long long u64;

// ---------------------------------------------------------------------------
// Per-hidden-unit weight record (6 ulonglong2 = 96B), all floats duplicated:
//  L0=(bias, w0) L1=(w4, w6) L2=(a1, a2) L3=(a3, b1) L4=(b2, b3) L5=(w2, 0)
// with a_i=(w_k+w_k')/2, b_i=(w_k-w_k')/2 over FLIP pairs (1,2),(3,5),(7,8).
// straight = base + SUM a*p + SUM b*q ; flipped = base + SUM a*p - SUM b*q
// where p=m_k+m_k', q=m_k-m_k'.  FLIP fixes {0,4,6}.
// ---------------------------------------------------------------------------
struct __align__(16) Params {
    ulonglong2 Wj[24][6];
    ulonglong2 Wn[24][6];
    float2 Mi6[9][6];
    float  jb2, nb2x2;
    float  pad[2];
};
__device__ Params g_p;

__global__ void prep_kernel(const float* __restrict__ jw1, const float* __restrict__ jb1,
                            const float* __restrict__ jw2, const float* __restrict__ jb2,
                            const float* __restrict__ nw1, const float* __restrict__ nb1,
                            const float* __restrict__ nw2, const float* __restrict__ nb2,
                            const float* __restrict__ M,   const float* __restrict__ Mi)
{
    (void)M;
    int t = threadIdx.x;
    if (t < 24) {
        int h = t;
        float2* wj = reinterpret_cast<float2*>(&g_p.Wj[h][0]);
        float2* wn = reinterpret_cast<float2*>(&g_p.Wn[h][0]);
        const float* J = jw1 + h * 9;
        const float* Nw = nw1 + h * 9;
        float v;
        v = jb1[h];               wj[0]  = make_float2(v, v);
        v = J[0];                 wj[1]  = make_float2(v, v);
        v = J[4];                 wj[2]  = make_float2(v, v);
        v = J[6];                 wj[3]  = make_float2(v, v);
        v = 0.5f * (J[1] + J[2]); wj[4]  = make_float2(v, v);  // a1
        v = 0.5f * (J[3] + J[5]); wj[5]  = make_float2(v, v);  // a2
        v = 0.5f * (J[7] + J[8]); wj[6]  = make_float2(v, v);  // a3
        v = 0.5f * (J[1] - J[2]); wj[7]  = make_float2(v, v);  // b1
        v = 0.5f * (J[3] - J[5]); wj[8]  = make_float2(v, v);  // b2
        v = 0.5f * (J[7] - J[8]); wj[9]  = make_float2(v, v);  // b3
        v = jw2[h];               wj[10] = make_float2(v, v);
        wj[11] = make_float2(0.f, 0.f);
        v = nb1[h];                 wn[0]  = make_float2(v, v);
        v = Nw[0];                  wn[1]  = make_float2(v, v);
        v = Nw[4];                  wn[2]  = make_float2(v, v);
        v = Nw[6];                  wn[3]  = make_float2(v, v);
        v = 0.5f * (Nw[1] + Nw[2]); wn[4]  = make_float2(v, v);
        v = 0.5f * (Nw[3] + Nw[5]); wn[5]  = make_float2(v, v);
        v = 0.5f * (Nw[7] + Nw[8]); wn[6]  = make_float2(v, v);
        v = 0.5f * (Nw[1] - Nw[2]); wn[7]  = make_float2(v, v);
        v = 0.5f * (Nw[3] - Nw[5]); wn[8]  = make_float2(v, v);
        v = 0.5f * (Nw[7] - Nw[8]); wn[9]  = make_float2(v, v);
        v = nw2[h];                 wn[10] = make_float2(v, v);
        wn[11] = make_float2(0.f, 0.f);
    }
    if (t < 9)
        for (int c = 0; c < 6; ++c) {
            float v = Mi[t * 9 + 3 + c];
            g_p.Mi6[t][c] = make_float2(v, v);
        }
    if (t == 0) { g_p.jb2 = jb2[0]; g_p.nb2x2 = 2.0f * nb2[0]; }
}

// ---------------------------------------------------------------------------
// f32x2 packed helpers
// ---------------------------------------------------------------------------
__device__ __forceinline__ u64 pk2(float lo, float hi) {
    u64 r; asm("mov.b64 %0, {%1, %2};" : "=l"(r) : "f"(lo), "f"(hi)); return r;
}
__device__ __forceinline__ void upk2(u64 v, float& lo, float& hi) {
    asm("mov.b64 {%0, %1}, %2;" : "=f"(lo), "=f"(hi) : "l"(v));
}
__device__ __forceinline__ u64 ffma2(u64 a, u64 b, u64 c) {
    u64 d; asm("fma.rn.f32x2 %0, %1, %2, %3;" : "=l"(d) : "l"(a), "l"(b), "l"(c)); return d;
}
__device__ __forceinline__ u64 fmul2(u64 a, u64 b) {
    u64 d; asm("mul.rn.f32x2 %0, %1, %2;" : "=l"(d) : "l"(a), "l"(b)); return d;
}
__device__ __forceinline__ u64 fadd2(u64 a, u64 b) {
    u64 d; asm("add.rn.f32x2 %0, %1, %2;" : "=l"(d) : "l"(a), "l"(b)); return d;
}
__device__ __forceinline__ float rcpa(float x) {
    float r; asm("rcp.approx.f32 %0, %1;" : "=f"(r) : "f"(x)); return r;
}
__device__ __forceinline__ u64 relu2(u64 x) {
    float a, b; upk2(x, a, b);
    return pk2(fmaxf(a, 0.0f), fmaxf(b, 0.0f));
}

#define NEGM 0x8000000080000000ULL

// Sparse hardcoded moment transform -> m0, m4, m6 and FLIP-pair basis
// pq = {p1,q1,p2,q2,p3,q3}, p_i = m_k + m_k', q_i = m_k - m_k'
// over pairs (1,2),(3,5),(7,8).
__device__ __forceinline__ void moments(const u64 (&f)[9],
                                        u64& m0, u64& m4, u64& m6, u64 (&pq)[6],
                                        u64 c_m2, u64 c_4, u64 c_m13)
{
    u64 nf3 = f[3] ^ NEGM, nf4 = f[4] ^ NEGM, nf7 = f[7] ^ NEGM, nf8 = f[8] ^ NEGM;
    u64 s58 = fadd2(f[5], f[8]);
    u64 s67 = fadd2(f[6], f[7]);
    u64 d58 = fadd2(f[5], nf8);
    u64 d67 = fadd2(f[6], nf7);
    u64 t13 = fadd2(f[1], nf3);
    u64 t24 = fadd2(f[2], nf4);
    u64 s13 = fadd2(f[1], f[3]);
    u64 s24 = fadd2(f[2], f[4]);
    u64 u = fadd2(s58, s67 ^ NEGM);        // f5-f6-f7+f8
    u64 v = fadd2(d58, d67);               // f5+f6-f7-f8
    u64 Q = fadd2(s58, s67);
    u64 P = fadd2(s13, s24);
    m0 = fadd2(f[0], fadd2(P, Q));
    m4 = fadd2(d58, d67 ^ NEGM);           // f5-f6+f7-f8
    m6 = ffma2(P, c_m2, ffma2(Q, c_4, f[0]));
    u64 m1 = fadd2(t13, u);
    u64 m2 = fadd2(t24, v);
    u64 m3 = ffma2(m0, c_m13, fadd2(s13, Q));
    u64 m5 = ffma2(m0, c_m13, fadd2(s24, Q));
    u64 m7 = ffma2(t13, c_m2, fmul2(u, c_4));
    u64 m8 = ffma2(t24, c_m2, fmul2(v, c_4));
    pq[0] = fadd2(m1, m2);
    pq[1] = fadd2(m1, m2 ^ NEGM);
    pq[2] = fadd2(m3, m5);
    pq[3] = fadd2(m3, m5 ^ NEGM);
    pq[4] = fadd2(m7, m8);
    pq[5] = fadd2(m7, m8 ^ NEGM);
}

__global__ __launch_bounds__(128, 5) void lbm_kernel(const float* __restrict__ f,
                                                     float* __restrict__ out, int N)
{
    __shared__ Params sp;
    {
        const uint4* src = reinterpret_cast<const uint4*>(&g_p);
        uint4* dst = reinterpret_cast<uint4*>(&sp);
        const int n16 = (int)(sizeof(Params) / 16);
        for (int i = threadIdx.x; i < n16; i += blockDim.x) dst[i] = src[i];
    }
    __syncthreads();

    long long idx = (long long)(blockIdx.x * blockDim.x + threadIdx.x) * 4;
    if (idx >= N) return;

    const u64 c_m2  = pk2(-2.0f, -2.0f);
    const u64 c_4   = pk2(4.0f, 4.0f);
    const u64 c_m13 = pk2(-1.0f / 3.0f, -1.0f / 3.0f);

    // ---- load f, compute moment basis; f regs die here (reloaded at output)
    u64 m0A, m4A, m6A, pqA[6];
    u64 m0B, m4B, m6B, pqB[6];
    {
        u64 fA[9], fB[9];
        #pragma unroll
        for (int i = 0; i < 9; ++i) {
            float4 v = *reinterpret_cast<const float4*>(f + (size_t)i * N + idx);
            fA[i] = pk2(v.x, v.y);
            fB[i] = pk2(v.z, v.w);
        }
        moments(fA, m0A, m4A, m6A, pqA, c_m2, c_4, c_m13);
        moments(fB, m0B, m4B, m6B, pqB, c_m2, c_4, c_m13);
    }

    // ---- fused j+n MLPs over 24 hidden units
    const ulonglong2* Wj = &sp.Wj[0][0];
    const ulonglong2* Wn = &sp.Wn[0][0];

    u64 jxA = pk2(sp.jb2, sp.jb2),     jxB = jxA;
    u64 jyA = jxA,                      jyB = jxA;
    u64 nnA = pk2(sp.nb2x2, sp.nb2x2), nnB = nnA;

    #pragma unroll 2
    for (int h = 0; h < 24; ++h) {
        // ---- j network
        {
            const ulonglong2* w = Wj + h * 6;
            ulonglong2 L0 = w[0], L1 = w[1], L2 = w[2], L3 = w[3], L4 = w[4], L5 = w[5];
            u64 tA = ffma2(L0.y, m0A, L0.x);
            u64 tB = ffma2(L0.y, m0B, L0.x);
            tA = ffma2(L1.x, m4A, tA);     tB = ffma2(L1.x, m4B, tB);
            tA = ffma2(L1.y, m6A, tA);     tB = ffma2(L1.y, m6B, tB);
            tA = ffma2(L2.x, pqA[0], tA);  tB = ffma2(L2.x, pqB[0], tB);
            tA = ffma2(L2.y, pqA[2], tA);  tB = ffma2(L2.y, pqB[2], tB);
            tA = ffma2(L3.x, pqA[4], tA);  tB = ffma2(L3.x, pqB[4], tB);
            u64 uA = fmul2(L3.y, pqA[1]);  u64 uB = fmul2(L3.y, pqB[1]);
            uA = ffma2(L4.x, pqA[3], uA);  uB = ffma2(L4.x, pqB[3], uB);
            uA = ffma2(L4.y, pqA[5], uA);  uB = ffma2(L4.y, pqB[5], uB);
            u64 sA = fadd2(tA, uA),        sB = fadd2(tB, uB);
            u64 fA = fadd2(tA, uA ^ NEGM), fB = fadd2(tB, uB ^ NEGM);
            jxA = ffma2(L5.x, relu2(sA), jxA);
            jxB = ffma2(L5.x, relu2(sB), jxB);
            jyA = ffma2(L5.x, relu2(fA), jyA);
            jyB = ffma2(L5.x, relu2(fB), jyB);
        }
        // ---- n network
        {
            const ulonglong2* w = Wn + h * 6;
            ulonglong2 L0 = w[0], L1 = w[1], L2 = w[2], L3 = w[3], L4 = w[4], L5 = w[5];
            u64 tA = ffma2(L0.y, m0A, L0.x);
            u64 tB = ffma2(L0.y, m0B, L0.x);
            tA = ffma2(L1.x, m4A, tA);     tB = ffma2(L1.x, m4B, tB);
            tA = ffma2(L1.y, m6A, tA);     tB = ffma2(L1.y, m6B, tB);
            tA = ffma2(L2.x, pqA[0], tA);  tB = ffma2(L2.x, pqB[0], tB);
            tA = ffma2(L2.y, pqA[2], tA);  tB = ffma2(L2.y, pqB[2], tB);
            tA = ffma2(L3.x, pqA[4], tA);  tB = ffma2(L3.x, pqB[4], tB);
            u64 uA = fmul2(L3.y, pqA[1]);  u64 uB = fmul2(L3.y, pqB[1]);
            uA = ffma2(L4.x, pqA[3], uA);  uB = ffma2(L4.x, pqB[3], uB);
            uA = ffma2(L4.y, pqA[5], uA);  uB = ffma2(L4.y, pqB[5], uB);
            u64 sA = fadd2(tA, uA),        sB = fadd2(tB, uB);
            u64 fA = fadd2(tA, uA ^ NEGM), fB = fadd2(tB, uB ^ NEGM);
            nnA = ffma2(L5.x, fadd2(relu2(sA), relu2(fA)), nnA);
            nnB = ffma2(L5.x, fadd2(relu2(sB), relu2(fB)), nnB);
        }
    }

    float jx0, jx1, jx2, jx3, jy0, jy1, jy2, jy3, nn0, nn1, nn2, nn3;
    upk2(jxA, jx0, jx1); upk2(jxB, jx2, jx3);
    upk2(jyA, jy0, jy1); upk2(jyB, jy2, jy3);
    upk2(nnA, nn0, nn1); upk2(nnB, nn2, nn3);

    // -1/tau = rcp(-(0.5+exp(a)))
    u64 ntnA = pk2(rcpa(-0.5f - __expf(nn0)), rcpa(-0.5f - __expf(nn1)));
    u64 ntnB = pk2(rcpa(-0.5f - __expf(nn2)), rcpa(-0.5f - __expf(nn3)));
    u64 ntxA = pk2(rcpa(-0.5f - __expf(jx0)), rcpa(-0.5f - __expf(jx1)));
    u64 ntxB = pk2(rcpa(-0.5f - __expf(jx2)), rcpa(-0.5f - __expf(jx3)));
    u64 ntyA = pk2(rcpa(-0.5f - __expf(jy0)), rcpa(-0.5f - __expf(jy1)));
    u64 ntyB = pk2(rcpa(-0.5f - __expf(jy2)), rcpa(-0.5f - __expf(jy3)));

    // ---- reconstruct m1,m2,m3,m5,m7,m8 from pq basis (exact to rounding)
    const u64 c_half = pk2(0.5f, 0.5f);
    u64 m1A = fmul2(fadd2(pqA[0], pqA[1]), c_half);
    u64 m2A = fmul2(fadd2(pqA[0], pqA[1] ^ NEGM), c_half);
    u64 m3A = fmul2(fadd2(pqA[2], pqA[3]), c_half);
    u64 m5A = fmul2(fadd2(pqA[2], pqA[3] ^ NEGM), c_half);
    u64 m7A = fmul2(fadd2(pqA[4], pqA[5]), c_half);
    u64 m8A = fmul2(fadd2(pqA[4], pqA[5] ^ NEGM), c_half);
    u64 m1B = fmul2(fadd2(pqB[0], pqB[1]), c_half);
    u64 m2B = fmul2(fadd2(pqB[0], pqB[1] ^ NEGM), c_half);
    u64 m3B = fmul2(fadd2(pqB[2], pqB[3]), c_half);
    u64 m5B = fmul2(fadd2(pqB[2], pqB[3] ^ NEGM), c_half);
    u64 m7B = fmul2(fadd2(pqB[4], pqB[5]), c_half);
    u64 m8B = fmul2(fadd2(pqB[4], pqB[5] ^ NEGM), c_half);

    // ---- ndm = (meq - m)/tau for rows 3..8 (rows 0..2 are zero)
    float r0, r1, r2, r3;
    upk2(m0A, r0, r1);
    upk2(m0B, r2, r3);
    u64 rAn = pk2(rcpa(-r0), rcpa(-r1));   // -1/rho
    u64 rBn = pk2(rcpa(-r2), rcpa(-r3));
    u64 jxrA = fmul2(m1A, rAn), jxrB = fmul2(m1B, rBn);  // -jx/rho
    u64 jyrA = fmul2(m2A, rAn), jyrB = fmul2(m2B, rBn);
    u64 e3A = fmul2(m1A, jxrA), e3B = fmul2(m1B, jxrB);  // -jx^2/rho
    u64 e4A = fmul2(m2A, jxrA), e4B = fmul2(m2B, jxrB);
    u64 e5A = fmul2(m2A, jyrA), e5B = fmul2(m2B, jyrB);

    const u64 c_ninv = pk2(-1.0f / 0.7f, -1.0f / 0.7f);
    u64 dmA[6], dmB[6];
    dmA[0] = fmul2(fadd2(m3A, e3A), c_ninv);
    dmB[0] = fmul2(fadd2(m3B, e3B), c_ninv);
    dmA[1] = fmul2(fadd2(m4A, e4A), c_ninv);
    dmB[1] = fmul2(fadd2(m4B, e4B), c_ninv);
    dmA[2] = fmul2(fadd2(m5A, e5A), c_ninv);
    dmB[2] = fmul2(fadd2(m5B, e5B), c_ninv);
    dmA[3] = fmul2(m6A, ntnA);
    dmB[3] = fmul2(m6B, ntnB);
    dmA[4] = fmul2(m7A, ntxA);
    dmB[4] = fmul2(m7B, ntxB);
    dmA[5] = fmul2(m8A, ntyA);
    dmB[5] = fmul2(m8B, ntyB);

    // ---- out_i = f_i + sum_c Minv[i][3+c] * ndm[c]   (f reloaded, L2-hot)
    const ulonglong2* Mi6 = reinterpret_cast<const ulonglong2*>(sp.Mi6);
    #pragma unroll
    for (int i = 0; i < 9; ++i) {
        float4 v = __ldg(reinterpret_cast<const float4*>(f + (size_t)i * N + idx));
        u64 a = pk2(v.x, v.y);
        u64 b = pk2(v.z, v.w);
        ulonglong2 W0 = Mi6[i * 3 + 0];
        ulonglong2 W1 = Mi6[i * 3 + 1];
        ulonglong2 W2 = Mi6[i * 3 + 2];
        a = ffma2(W0.x, dmA[0], a);  b = ffma2(W0.x, dmB[0], b);
        a = ffma2(W0.y, dmA[1], a);  b = ffma2(W0.y, dmB[1], b);
        a = ffma2(W1.x, dmA[2], a);  b = ffma2(W1.x, dmB[2], b);
        a = ffma2(W1.y, dmA[3], a);  b = ffma2(W1.y, dmB[3], b);
        a = ffma2(W2.x, dmA[4], a);  b = ffma2(W2.x, dmB[4], b);
        a = ffma2(W2.y, dmA[5], a);  b = ffma2(W2.y, dmB[5], b);
        float o0, o1, o2, o3;
        upk2(a, o0, o1);
        upk2(b, o2, o3);
        *reinterpret_cast<float4*>(out + (size_t)i * N + idx) = make_float4(o0, o1, o2, o3);
    }
}

extern "C" void kernel_launch(void* const* d_in, const int* in_sizes, int n_in,
                              void* d_out, int out_size)
{
    // input order: f, j_w1, j_b1, j_w2, j_b2, n_w1, n_b1, n_w2, n_b2, M, Minv
    const float* f = (const float*)d_in[0];
    prep_kernel<<<1, 96>>>((const float*)d_in[1], (const float*)d_in[2],
                           (const float*)d_in[3], (const float*)d_in[4],
                           (const float*)d_in[5], (const float*)d_in[6],
                           (const float*)d_in[7], (const float*)d_in[8],
                           (const float*)d_in[9], (const float*)d_in[10]);

    int N = in_sizes[0] / 9;                 // 2048*2048 cells
    int threads = (N + 3) / 4;               // 4 cells per thread
    int block = 128;
    int grid = (threads + block - 1) / block;
    lbm_kernel<<<grid, block>>>(f, (float*)d_out, N);
}

// round 5
// speedup vs baseline: 1.3623x; 1.0811x over previous
#include <cuda_runtime.h>
#include <cstdint>

typedef unsigned long long u64;

// ---------------------------------------------------------------------------
// Per-hidden-unit weight record (6 ulonglong2 = 96B), all floats duplicated:
//  L0=(bias, w0) L1=(w4, w6) L2=(a1, a2) L3=(a3, b1) L4=(b2, b3) L5=(w2, 0)
// with a_i=(w_k+w_k')/2, b_i=(w_k-w_k')/2 over FLIP pairs (1,2),(3,5),(7,8).
// straight = base + SUM a*p + SUM b*q ; flipped = base + SUM a*p - SUM b*q
// where p=m_k+m_k', q=m_k-m_k'.  FLIP fixes {0,4,6}.
// Minv columns 3..5 (relative dm rows 0..2) are pre-scaled by -1/0.7.
// ---------------------------------------------------------------------------
struct __align__(16) Params {
    ulonglong2 Wj[24][6];
    ulonglong2 Wn[24][6];
    float2 Mi6[9][6];
    float  jb2, nb2x2;
    float  pad[2];
};
__device__ Params g_p;

__global__ void prep_kernel(const float* __restrict__ jw1, const float* __restrict__ jb1,
                            const float* __restrict__ jw2, const float* __restrict__ jb2,
                            const float* __restrict__ nw1, const float* __restrict__ nb1,
                            const float* __restrict__ nw2, const float* __restrict__ nb2,
                            const float* __restrict__ M,   const float* __restrict__ Mi)
{
    (void)M;
    int t = threadIdx.x;
    if (t < 24) {
        int h = t;
        float2* wj = reinterpret_cast<float2*>(&g_p.Wj[h][0]);
        float2* wn = reinterpret_cast<float2*>(&g_p.Wn[h][0]);
        const float* J = jw1 + h * 9;
        const float* Nw = nw1 + h * 9;
        float v;
        v = jb1[h];               wj[0]  = make_float2(v, v);
        v = J[0];                 wj[1]  = make_float2(v, v);
        v = J[4];                 wj[2]  = make_float2(v, v);
        v = J[6];                 wj[3]  = make_float2(v, v);
        v = 0.5f * (J[1] + J[2]); wj[4]  = make_float2(v, v);  // a1
        v = 0.5f * (J[3] + J[5]); wj[5]  = make_float2(v, v);  // a2
        v = 0.5f * (J[7] + J[8]); wj[6]  = make_float2(v, v);  // a3
        v = 0.5f * (J[1] - J[2]); wj[7]  = make_float2(v, v);  // b1
        v = 0.5f * (J[3] - J[5]); wj[8]  = make_float2(v, v);  // b2
        v = 0.5f * (J[7] - J[8]); wj[9]  = make_float2(v, v);  // b3
        v = jw2[h];               wj[10] = make_float2(v, v);
        wj[11] = make_float2(0.f, 0.f);
        v = nb1[h];                 wn[0]  = make_float2(v, v);
        v = Nw[0];                  wn[1]  = make_float2(v, v);
        v = Nw[4];                  wn[2]  = make_float2(v, v);
        v = Nw[6];                  wn[3]  = make_float2(v, v);
        v = 0.5f * (Nw[1] + Nw[2]); wn[4]  = make_float2(v, v);
        v = 0.5f * (Nw[3] + Nw[5]); wn[5]  = make_float2(v, v);
        v = 0.5f * (Nw[7] + Nw[8]); wn[6]  = make_float2(v, v);
        v = 0.5f * (Nw[1] - Nw[2]); wn[7]  = make_float2(v, v);
        v = 0.5f * (Nw[3] - Nw[5]); wn[8]  = make_float2(v, v);
        v = 0.5f * (Nw[7] - Nw[8]); wn[9]  = make_float2(v, v);
        v = nw2[h];                 wn[10] = make_float2(v, v);
        wn[11] = make_float2(0.f, 0.f);
    }
    if (t < 9)
        for (int c = 0; c < 6; ++c) {
            float v = Mi[t * 9 + 3 + c];
            if (c < 3) v *= -1.0f / 0.7f;   // fold tau=0.7 relaxation scale
            g_p.Mi6[t][c] = make_float2(v, v);
        }
    if (t == 0) { g_p.jb2 = jb2[0]; g_p.nb2x2 = 2.0f * nb2[0]; }
}

// ---------------------------------------------------------------------------
// f32x2 packed helpers
// ---------------------------------------------------------------------------
__device__ __forceinline__ u64 pk2(float lo, float hi) {
    u64 r; asm("mov.b64 %0, {%1, %2};" : "=l"(r) : "f"(lo), "f"(hi)); return r;
}
__device__ __forceinline__ void upk2(u64 v, float& lo, float& hi) {
    asm("mov.b64 {%0, %1}, %2;" : "=f"(lo), "=f"(hi) : "l"(v));
}
__device__ __forceinline__ u64 ffma2(u64 a, u64 b, u64 c) {
    u64 d; asm("fma.rn.f32x2 %0, %1, %2, %3;" : "=l"(d) : "l"(a), "l"(b), "l"(c)); return d;
}
__device__ __forceinline__ u64 fmul2(u64 a, u64 b) {
    u64 d; asm("mul.rn.f32x2 %0, %1, %2;" : "=l"(d) : "l"(a), "l"(b)); return d;
}
__device__ __forceinline__ u64 fadd2(u64 a, u64 b) {
    u64 d; asm("add.rn.f32x2 %0, %1, %2;" : "=l"(d) : "l"(a), "l"(b)); return d;
}
__device__ __forceinline__ u64 fsub2(u64 a, u64 b) {
    u64 d; asm("sub.rn.f32x2 %0, %1, %2;" : "=l"(d) : "l"(a), "l"(b)); return d;
}
__device__ __forceinline__ float rcpa(float x) {
    float r; asm("rcp.approx.f32 %0, %1;" : "=f"(r) : "f"(x)); return r;
}
__device__ __forceinline__ u64 relu2(u64 x) {
    float a, b; upk2(x, a, b);
    return pk2(fmaxf(a, 0.0f), fmaxf(b, 0.0f));
}

// Sparse hardcoded moment transform -> m0, m4, m6 and FLIP-pair basis
// pq = {p1,q1,p2,q2,p3,q3}, p_i = m_k + m_k', q_i = m_k - m_k'
// over pairs (1,2),(3,5),(7,8).  XOR-free: all negations via sub.rn.f32x2.
__device__ __forceinline__ void moments(const u64 (&f)[9],
                                        u64& m0, u64& m4, u64& m6, u64 (&pq)[6],
                                        u64 c_m2, u64 c_4, u64 c_m13)
{
    u64 s58 = fadd2(f[5], f[8]);
    u64 s67 = fadd2(f[6], f[7]);
    u64 d58 = fsub2(f[5], f[8]);
    u64 d67 = fsub2(f[6], f[7]);
    u64 t13 = fsub2(f[1], f[3]);
    u64 t24 = fsub2(f[2], f[4]);
    u64 s13 = fadd2(f[1], f[3]);
    u64 s24 = fadd2(f[2], f[4]);
    u64 u = fsub2(s58, s67);               // f5-f6-f7+f8
    u64 v = fadd2(d58, d67);               // f5+f6-f7-f8
    u64 Q = fadd2(s58, s67);
    u64 P = fadd2(s13, s24);
    m0 = fadd2(f[0], fadd2(P, Q));
    m4 = fsub2(d58, d67);                  // f5-f6+f7-f8
    m6 = ffma2(P, c_m2, ffma2(Q, c_4, f[0]));
    u64 m1 = fadd2(t13, u);
    u64 m2 = fadd2(t24, v);
    u64 m3 = ffma2(m0, c_m13, fadd2(s13, Q));
    u64 m5 = ffma2(m0, c_m13, fadd2(s24, Q));
    u64 m7 = ffma2(t13, c_m2, fmul2(u, c_4));
    u64 m8 = ffma2(t24, c_m2, fmul2(v, c_4));
    pq[0] = fadd2(m1, m2);
    pq[1] = fsub2(m1, m2);
    pq[2] = fadd2(m3, m5);
    pq[3] = fsub2(m3, m5);
    pq[4] = fadd2(m7, m8);
    pq[5] = fsub2(m7, m8);
}

__global__ __launch_bounds__(128, 6) void lbm_kernel(const float* __restrict__ f,
                                                     float* __restrict__ out, int N)
{
    __shared__ Params sp;
    {
        const uint4* src = reinterpret_cast<const uint4*>(&g_p);
        uint4* dst = reinterpret_cast<uint4*>(&sp);
        const int n16 = (int)(sizeof(Params) / 16);
        for (int i = threadIdx.x; i < n16; i += blockDim.x) dst[i] = src[i];
    }
    __syncthreads();

    int idx = (blockIdx.x * blockDim.x + threadIdx.x) * 4;
    if (idx >= N) return;

    const u64 c_m2  = pk2(-2.0f, -2.0f);
    const u64 c_4   = pk2(4.0f, 4.0f);
    const u64 c_m13 = pk2(-1.0f / 3.0f, -1.0f / 3.0f);

    // ---- load f, compute moment basis; f regs die here (reloaded at output)
    u64 m0A, m4A, m6A, pqA[6];
    u64 m0B, m4B, m6B, pqB[6];
    {
        u64 fA[9], fB[9];
        #pragma unroll
        for (int i = 0; i < 9; ++i) {
            float4 v = *reinterpret_cast<const float4*>(f + i * N + idx);
            fA[i] = pk2(v.x, v.y);
            fB[i] = pk2(v.z, v.w);
        }
        moments(fA, m0A, m4A, m6A, pqA, c_m2, c_4, c_m13);
        moments(fB, m0B, m4B, m6B, pqB, c_m2, c_4, c_m13);
    }

    // ---- fused j+n MLPs over 24 hidden units
    const ulonglong2* Wj = &sp.Wj[0][0];
    const ulonglong2* Wn = &sp.Wn[0][0];

    u64 jxA = pk2(sp.jb2, sp.jb2),     jxB = jxA;
    u64 jyA = jxA,                      jyB = jxA;
    u64 nnA = pk2(sp.nb2x2, sp.nb2x2), nnB = nnA;

    #pragma unroll 2
    for (int h = 0; h < 24; ++h) {
        // ---- j network
        {
            const ulonglong2* w = Wj + h * 6;
            ulonglong2 L0 = w[0], L1 = w[1], L2 = w[2], L3 = w[3], L4 = w[4], L5 = w[5];
            u64 tA = ffma2(L0.y, m0A, L0.x);
            u64 tB = ffma2(L0.y, m0B, L0.x);
            tA = ffma2(L1.x, m4A, tA);     tB = ffma2(L1.x, m4B, tB);
            tA = ffma2(L1.y, m6A, tA);     tB = ffma2(L1.y, m6B, tB);
            tA = ffma2(L2.x, pqA[0], tA);  tB = ffma2(L2.x, pqB[0], tB);
            tA = ffma2(L2.y, pqA[2], tA);  tB = ffma2(L2.y, pqB[2], tB);
            tA = ffma2(L3.x, pqA[4], tA);  tB = ffma2(L3.x, pqB[4], tB);
            u64 uA = fmul2(L3.y, pqA[1]);  u64 uB = fmul2(L3.y, pqB[1]);
            uA = ffma2(L4.x, pqA[3], uA);  uB = ffma2(L4.x, pqB[3], uB);
            uA = ffma2(L4.y, pqA[5], uA);  uB = ffma2(L4.y, pqB[5], uB);
            u64 sA = fadd2(tA, uA),        sB = fadd2(tB, uB);
            u64 fA = fsub2(tA, uA),        fB = fsub2(tB, uB);
            jxA = ffma2(L5.x, relu2(sA), jxA);
            jxB = ffma2(L5.x, relu2(sB), jxB);
            jyA = ffma2(L5.x, relu2(fA), jyA);
            jyB = ffma2(L5.x, relu2(fB), jyB);
        }
        // ---- n network
        {
            const ulonglong2* w = Wn + h * 6;
            ulonglong2 L0 = w[0], L1 = w[1], L2 = w[2], L3 = w[3], L4 = w[4], L5 = w[5];
            u64 tA = ffma2(L0.y, m0A, L0.x);
            u64 tB = ffma2(L0.y, m0B, L0.x);
            tA = ffma2(L1.x, m4A, tA);     tB = ffma2(L1.x, m4B, tB);
            tA = ffma2(L1.y, m6A, tA);     tB = ffma2(L1.y, m6B, tB);
            tA = ffma2(L2.x, pqA[0], tA);  tB = ffma2(L2.x, pqB[0], tB);
            tA = ffma2(L2.y, pqA[2], tA);  tB = ffma2(L2.y, pqB[2], tB);
            tA = ffma2(L3.x, pqA[4], tA);  tB = ffma2(L3.x, pqB[4], tB);
            u64 uA = fmul2(L3.y, pqA[1]);  u64 uB = fmul2(L3.y, pqB[1]);
            uA = ffma2(L4.x, pqA[3], uA);  uB = ffma2(L4.x, pqB[3], uB);
            uA = ffma2(L4.y, pqA[5], uA);  uB = ffma2(L4.y, pqB[5], uB);
            u64 sA = fadd2(tA, uA),        sB = fadd2(tB, uB);
            u64 fA = fsub2(tA, uA),        fB = fsub2(tB, uB);
            nnA = ffma2(L5.x, fadd2(relu2(sA), relu2(fA)), nnA);
            nnB = ffma2(L5.x, fadd2(relu2(sB), relu2(fB)), nnB);
        }
    }

    float jx0, jx1, jx2, jx3, jy0, jy1, jy2, jy3, nn0, nn1, nn2, nn3;
    upk2(jxA, jx0, jx1); upk2(jxB, jx2, jx3);
    upk2(jyA, jy0, jy1); upk2(jyB, jy2, jy3);
    upk2(nnA, nn0, nn1); upk2(nnB, nn2, nn3);

    // -1/tau = rcp(-(0.5+exp(a)))
    u64 ntnA = pk2(rcpa(-0.5f - __expf(nn0)), rcpa(-0.5f - __expf(nn1)));
    u64 ntnB = pk2(rcpa(-0.5f - __expf(nn2)), rcpa(-0.5f - __expf(nn3)));
    u64 ntxA = pk2(rcpa(-0.5f - __expf(jx0)), rcpa(-0.5f - __expf(jx1)));
    u64 ntxB = pk2(rcpa(-0.5f - __expf(jx2)), rcpa(-0.5f - __expf(jx3)));
    u64 ntyA = pk2(rcpa(-0.5f - __expf(jy0)), rcpa(-0.5f - __expf(jy1)));
    u64 ntyB = pk2(rcpa(-0.5f - __expf(jy2)), rcpa(-0.5f - __expf(jy3)));

    // ---- reconstruct m1,m2,m3,m5,m7,m8 from pq basis (exact to rounding)
    const u64 c_half = pk2(0.5f, 0.5f);
    u64 m1A = fmul2(fadd2(pqA[0], pqA[1]), c_half);
    u64 m2A = fmul2(fsub2(pqA[0], pqA[1]), c_half);
    u64 m3A = fmul2(fadd2(pqA[2], pqA[3]), c_half);
    u64 m5A = fmul2(fsub2(pqA[2], pqA[3]), c_half);
    u64 m7A = fmul2(fadd2(pqA[4], pqA[5]), c_half);
    u64 m8A = fmul2(fsub2(pqA[4], pqA[5]), c_half);
    u64 m1B = fmul2(fadd2(pqB[0], pqB[1]), c_half);
    u64 m2B = fmul2(fsub2(pqB[0], pqB[1]), c_half);
    u64 m3B = fmul2(fadd2(pqB[2], pqB[3]), c_half);
    u64 m5B = fmul2(fsub2(pqB[2], pqB[3]), c_half);
    u64 m7B = fmul2(fadd2(pqB[4], pqB[5]), c_half);
    u64 m8B = fmul2(fsub2(pqB[4], pqB[5]), c_half);

    // ---- dm rows (relaxation scale for rows 0..2 folded into Mi6)
    float r0, r1, r2, r3;
    upk2(m0A, r0, r1);
    upk2(m0B, r2, r3);
    u64 rAn = pk2(rcpa(-r0), rcpa(-r1));   // -1/rho
    u64 rBn = pk2(rcpa(-r2), rcpa(-r3));
    u64 jxrA = fmul2(m1A, rAn), jxrB = fmul2(m1B, rBn);  // -jx/rho
    u64 jyrA = fmul2(m2A, rAn), jyrB = fmul2(m2B, rBn);
    u64 e3A = fmul2(m1A, jxrA), e3B = fmul2(m1B, jxrB);  // -jx^2/rho
    u64 e4A = fmul2(m2A, jxrA), e4B = fmul2(m2B, jxrB);
    u64 e5A = fmul2(m2A, jyrA), e5B = fmul2(m2B, jyrB);

    u64 dmA[6], dmB[6];
    dmA[0] = fadd2(m3A, e3A);   // m - meq   (x -1/0.7 folded into Mi6)
    dmB[0] = fadd2(m3B, e3B);
    dmA[1] = fadd2(m4A, e4A);
    dmB[1] = fadd2(m4B, e4B);
    dmA[2] = fadd2(m5A, e5A);
    dmB[2] = fadd2(m5B, e5B);
    dmA[3] = fmul2(m6A, ntnA);  // -m/tau
    dmB[3] = fmul2(m6B, ntnB);
    dmA[4] = fmul2(m7A, ntxA);
    dmB[4] = fmul2(m7B, ntxB);
    dmA[5] = fmul2(m8A, ntyA);
    dmB[5] = fmul2(m8B, ntyB);

    // ---- out_i = f_i + sum_c Mi6[i][c] * dm[c]   (f reloaded, L2-hot)
    const ulonglong2* Mi6 = reinterpret_cast<const ulonglong2*>(sp.Mi6);
    #pragma unroll
    for (int i = 0; i < 9; ++i) {
        float4 v = __ldg(reinterpret_cast<const float4*>(f + i * N + idx));
        u64 a = pk2(v.x, v.y);
        u64 b = pk2(v.z, v.w);
        ulonglong2 W0 = Mi6[i * 3 + 0];
        ulonglong2 W1 = Mi6[i * 3 + 1];
        ulonglong2 W2 = Mi6[i * 3 + 2];
        a = ffma2(W0.x, dmA[0], a);  b = ffma2(W0.x, dmB[0], b);
        a = ffma2(W0.y, dmA[1], a);  b = ffma2(W0.y, dmB[1], b);
        a = ffma2(W1.x, dmA[2], a);  b = ffma2(W1.x, dmB[2], b);
        a = ffma2(W1.y, dmA[3], a);  b = ffma2(W1.y, dmB[3], b);
        a = ffma2(W2.x, dmA[4], a);  b = ffma2(W2.x, dmB[4], b);
        a = ffma2(W2.y, dmA[5], a);  b = ffma2(W2.y, dmB[5], b);
        float o0, o1, o2, o3;
        upk2(a, o0, o1);
        upk2(b, o2, o3);
        *reinterpret_cast<float4*>(out + i * N + idx) = make_float4(o0, o1, o2, o3);
    }
}

extern "C" void kernel_launch(void* const* d_in, const int* in_sizes, int n_in,
                              void* d_out, int out_size)
{
    // input order: f, j_w1, j_b1, j_w2, j_b2, n_w1, n_b1, n_w2, n_b2, M, Minv
    const float* f = (const float*)d_in[0];
    prep_kernel<<<1, 96>>>((const float*)d_in[1], (const float*)d_in[2],
                           (const float*)d_in[3], (const float*)d_in[4],
                           (const float*)d_in[5], (const float*)d_in[6],
                           (const float*)d_in[7], (const float*)d_in[8],
                           (const float*)d_in[9], (const float*)d_in[10]);

    int N = in_sizes[0] / 9;                 // 2048*2048 cells
    int threads = (N + 3) / 4;               // 4 cells per thread
    int block = 128;
    int grid = (threads + block - 1) / block;
    lbm_kernel<<<grid, block>>>(f, (float*)d_out, N);
}